// round 14
// baseline (speedup 1.0000x reference)
#include <cuda_runtime.h>
#include <cuda_fp16.h>
#include <math.h>

#define N_NODES 40000
#define E_EDGES 200000
#define DIM 256
#define NHEAD 8
#define NODE_F (N_NODES * DIM)
#define PAD_F (64 * DIM)
#define NSEG (3 * N_NODES)

// ---------------- scratch (device globals) ----------------
__device__ __half g_hrh[2][NODE_F + PAD_F];   // fp16 copies of h_A, h_B (natural layout)
__device__ __half g_Qh[2][NODE_F];
__device__ __half g_kh[3][NODE_F];
__device__ __half g_vh[3][NODE_F];
__device__ __half g_WTh[2048 * 256];          // K-major concat weights, fp16
__device__ float  g_bc[2048];
__device__ __half g_WaTh[2 * 256 * 256];      // Wa^T, K-major, fp16
__device__ __half g_tth[2][NODE_F + PAD_F];   // combined features, fp16
__device__ int    g_hist[NSEG];               // zero at load; scan re-zeroes each run
__device__ int    g_rowptr[NSEG];
__device__ int    g_cursor[NSEG];             // after scatter: cursor[seg] == segment end
__device__ int    g_total;                    // zero at load; scatter re-zeroes each run
__device__ int    g_csr[3 * E_EDGES];

struct Job {
    const __half* A; const __half* W; const float* bias; void* outp;
    const float* Hres; const float* skipv; int cin; int mode;
};
struct Jobs { Job j[16]; };

// ---------------- helpers ----------------
__device__ __forceinline__ unsigned pack2(float a, float b) {
    __half2 h = __floats2half2_rn(a, b);
    return *(unsigned*)&h;
}
__device__ __forceinline__ void mma_f16(float* d, const unsigned* a, unsigned b0, unsigned b1) {
    asm volatile(
        "mma.sync.aligned.m16n8k16.row.col.f32.f16.f16.f32 "
        "{%0,%1,%2,%3}, {%4,%5,%6,%7}, {%8,%9}, {%0,%1,%2,%3};"
        : "+f"(d[0]), "+f"(d[1]), "+f"(d[2]), "+f"(d[3])
        : "r"(a[0]), "r"(a[1]), "r"(a[2]), "r"(a[3]), "r"(b0), "r"(b1));
}
__device__ __forceinline__ void ldm_x4(unsigned* r, unsigned addr) {
    asm volatile("ldmatrix.sync.aligned.m8n8.x4.shared.b16 {%0,%1,%2,%3}, [%4];"
                 : "=r"(r[0]), "=r"(r[1]), "=r"(r[2]), "=r"(r[3]) : "r"(addr));
}
__device__ __forceinline__ void cpa16(unsigned saddr, const void* g) {
    asm volatile("cp.async.cg.shared.global [%0], [%1], 16;" :: "r"(saddr), "l"(g));
}
__device__ __forceinline__ unsigned smem_u32(const void* p) {
    unsigned a;
    asm("{ .reg .u64 t; cvta.to.shared.u64 t, %1; cvt.u32.u64 %0, t; }" : "=r"(a) : "l"(p));
    return a;
}
__device__ __forceinline__ void ld8h_nc(const __half* p, float* f) {
    uint4 u = __ldg((const uint4*)p);
    float2 a;
    a = __half22float2(*(__half2*)&u.x); f[0] = a.x; f[1] = a.y;
    a = __half22float2(*(__half2*)&u.y); f[2] = a.x; f[3] = a.y;
    a = __half22float2(*(__half2*)&u.z); f[4] = a.x; f[5] = a.y;
    a = __half22float2(*(__half2*)&u.w); f[6] = a.x; f[7] = a.y;
}
__device__ __forceinline__ float dot8h(const __half2* qh, uint4 ku) {
    __half2 acc = __hmul2(qh[0], *(__half2*)&ku.x);
    acc = __hfma2(qh[1], *(__half2*)&ku.y, acc);
    acc = __hfma2(qh[2], *(__half2*)&ku.z, acc);
    acc = __hfma2(qh[3], *(__half2*)&ku.w, acc);
    float2 f = __half22float2(acc);
    return f.x + f.y;
}

// ---------------- prep: round inputs + build weights/biases + dst histogram ----------------
#define NGRP  (NODE_F / 16)
#define TOTW  (2048 * 256)
#define TOTB  2048
#define TOTWA (2 * 256 * 256)
#define PREP_BASE (NGRP + TOTW + TOTB + TOTWA)
__global__ void prep_kernel(const float* __restrict__ hA, const float* __restrict__ hB,
                            const float* __restrict__ Wq, const float* __restrict__ bq,
                            const float* __restrict__ Wk, const float* __restrict__ bk,
                            const float* __restrict__ Wv, const float* __restrict__ bv,
                            const float* __restrict__ Wa,
                            const float* __restrict__ rel_att, const float* __restrict__ rel_msg,
                            const int* __restrict__ d0, const int* __restrict__ d1,
                            const int* __restrict__ d2, int E) {
    int gid = blockIdx.x * blockDim.x + threadIdx.x;
    if (gid < NGRP) {
        int i = gid;
        #pragma unroll
        for (int t = 0; t < 2; t++) {
            const float* src = t ? hB : hA;
            float4 f0 = ((const float4*)src)[4 * i + 0];
            float4 f1 = ((const float4*)src)[4 * i + 1];
            float4 f2 = ((const float4*)src)[4 * i + 2];
            float4 f3 = ((const float4*)src)[4 * i + 3];
            ((uint4*)g_hrh[t])[2 * i]     = make_uint4(pack2(f0.x, f0.y), pack2(f0.z, f0.w),
                                                       pack2(f1.x, f1.y), pack2(f1.z, f1.w));
            ((uint4*)g_hrh[t])[2 * i + 1] = make_uint4(pack2(f2.x, f2.y), pack2(f2.z, f2.w),
                                                       pack2(f3.x, f3.y), pack2(f3.z, f3.w));
        }
        return;
    }
    gid -= NGRP;
    if (gid < TOTW) {
        int k = gid & 255;
        int n = gid >> 8;
        int side  = (n < 1280) ? 0 : 1;
        int local = side ? (n - 1280) : n;
        int g = local >> 8, col = local & 255;
        float val;
        if (g == 0) {
            val = Wq[side * 65536 + k * 256 + col];
        } else {
            int r   = side ? 1 : ((g <= 2) ? 0 : 2);
            int isv = side ? (g == 2) : ((g & 1) == 0);
            const float* W  = (isv ? Wv : Wk) + side * 65536 + k * 256 + (col >> 5) * 32;
            const float* rp = (isv ? rel_msg : rel_att) + r * 8192 + (col >> 5) * 1024 + (col & 31);
            float acc = 0.f;
            #pragma unroll
            for (int d = 0; d < 32; d++) acc += W[d] * rp[d * 32];
            val = acc;
        }
        g_WTh[n * 256 + k] = __float2half_rn(val);
        return;
    }
    gid -= TOTW;
    if (gid < TOTB) {
        int n = gid;
        int side  = (n < 1280) ? 0 : 1;
        int local = side ? (n - 1280) : n;
        int g = local >> 8, col = local & 255;
        float val;
        if (g == 0) {
            val = bq[side * 256 + col];
        } else {
            int r   = side ? 1 : ((g <= 2) ? 0 : 2);
            int isv = side ? (g == 2) : ((g & 1) == 0);
            const float* b  = (isv ? bv : bk) + side * 256 + (col >> 5) * 32;
            const float* rp = (isv ? rel_msg : rel_att) + r * 8192 + (col >> 5) * 1024 + (col & 31);
            float acc = 0.f;
            #pragma unroll
            for (int d = 0; d < 32; d++) acc += b[d] * rp[d * 32];
            val = acc;
        }
        g_bc[n] = val;
        return;
    }
    gid -= TOTB;
    if (gid < TOTWA) {
        int i = gid;
        int k = i & 255, nn = (i >> 8) & 255, t = i >> 16;
        g_WaTh[t * 65536 + nn * 256 + k] = __float2half_rn(Wa[t * 65536 + k * 256 + nn]);
        return;
    }
    gid -= TOTWA;
    if (gid < 3 * E) {
        int r = gid / E, e = gid - r * E;
        const int* dd = (r == 0) ? d0 : ((r == 1) ? d1 : d2);
        atomicAdd(&g_hist[r * N_NODES + dd[e]], 1);
    }
}

// ---------------- fp16 mma.sync GEMM, ldmatrix fragments, cp.async 2-stage ----------------
// CTA tile 128x128, warp tile 64x32 (2x4 warps), K-chunks of 64 halves (128B/row),
// smem row stride 144B (36 words) -> ldmatrix conflict-free.
#define ROWB 144u
#define STG_BYTES 36864u          // per stage: A(128*144) + B(128*144)
#define TG_SMEM 73728
__global__ void __launch_bounds__(256, 2) tgemm(Jobs jobs, int M) {
    extern __shared__ float smem[];
    unsigned sbase = smem_u32(smem);
    Job jb = jobs.j[blockIdx.x];
    int tid = threadIdx.x, lane = tid & 31, wid = tid >> 5;
    int row0 = blockIdx.y * 128;
    int wm = (wid >> 2) * 64;
    int wn = (wid & 3) * 32;
    int g = lane >> 2, c = lane & 3;

    float acc[4][4][4];
    #pragma unroll
    for (int i = 0; i < 4; i++)
        #pragma unroll
        for (int j = 0; j < 4; j++)
            #pragma unroll
            for (int q = 0; q < 4; q++) acc[i][j][q] = 0.f;

    // cp.async staging: 1024 16B-segments per operand per chunk; 4 per thread
    int r_st[4], sg_st[4];
    #pragma unroll
    for (int i = 0; i < 4; i++) {
        int sl = i * 256 + tid;
        r_st[i] = sl >> 3; sg_st[i] = sl & 7;
    }

    // ldmatrix lane addressing
    int lr = lane & 7;
    unsigned aOff = (unsigned)((wm + lr + ((lane >> 3) & 1) * 8) * ROWB + (lane >> 4) * 16);
    unsigned bOff = (unsigned)(18432u + (wn + lr + (lane >> 4) * 8) * ROWB + ((lane >> 3) & 1) * 16);

    // prefetch chunk 0 -> stage 0
    #pragma unroll
    for (int i = 0; i < 4; i++) {
        unsigned so = sbase + (unsigned)r_st[i] * ROWB + (unsigned)sg_st[i] * 16u;
        cpa16(so, jb.A + (size_t)(row0 + r_st[i]) * 256 + sg_st[i] * 8);
        cpa16(so + 18432u, jb.W + (size_t)r_st[i] * 256 + sg_st[i] * 8);
    }
    asm volatile("cp.async.commit_group;" ::: "memory");

    #pragma unroll
    for (int ck = 0; ck < 4; ck++) {
        asm volatile("cp.async.wait_group 0;" ::: "memory");
        __syncthreads();
        if (ck + 1 < 4) {
            unsigned stb = sbase + ((ck + 1) & 1) * STG_BYTES;
            #pragma unroll
            for (int i = 0; i < 4; i++) {
                unsigned so = stb + (unsigned)r_st[i] * ROWB + (unsigned)sg_st[i] * 16u;
                cpa16(so, jb.A + (size_t)(row0 + r_st[i]) * 256 + (ck + 1) * 64 + sg_st[i] * 8);
                cpa16(so + 18432u, jb.W + (size_t)r_st[i] * 256 + (ck + 1) * 64 + sg_st[i] * 8);
            }
            asm volatile("cp.async.commit_group;" ::: "memory");
        }
        unsigned stg = sbase + (ck & 1) * STG_BYTES;
        #pragma unroll
        for (int s = 0; s < 4; s++) {
            unsigned af[4][4], bf[2][4];
            #pragma unroll
            for (int mt = 0; mt < 4; mt++)
                ldm_x4(af[mt], stg + aOff + (unsigned)(mt * 16 * ROWB) + (unsigned)(s * 32));
            #pragma unroll
            for (int p = 0; p < 2; p++)
                ldm_x4(bf[p], stg + bOff + (unsigned)(p * 16 * ROWB) + (unsigned)(s * 32));
            #pragma unroll
            for (int mt = 0; mt < 4; mt++) {
                #pragma unroll
                for (int nt = 0; nt < 4; nt++) {
                    unsigned b0 = bf[nt >> 1][(nt & 1) * 2];
                    unsigned b1 = bf[nt >> 1][(nt & 1) * 2 + 1];
                    mma_f16(acc[mt][nt], af[mt], b0, b1);
                }
            }
        }
    }

    float alpha = 1.f, beta = 0.f;
    if (jb.mode == 1) {
        float sv = *jb.skipv;
        alpha = 1.f / (1.f + __expf(-sv));
        beta  = 1.f - alpha;
    }
    int cinb = jb.cin + wn;
    #pragma unroll
    for (int mt = 0; mt < 4; mt++) {
        #pragma unroll
        for (int half = 0; half < 2; half++) {
            int row = row0 + wm + mt * 16 + g + half * 8;
            if (row >= M) continue;
            #pragma unroll
            for (int nt = 0; nt < 4; nt++) {
                int lcol = wn + nt * 8 + 2 * c;
                int cin = cinb + nt * 8 + 2 * c;
                float v0 = acc[mt][nt][half * 2 + 0] + jb.bias[lcol];
                float v1 = acc[mt][nt][half * 2 + 1] + jb.bias[lcol + 1];
                if (jb.mode == 1) {
                    float* O = (float*)jb.outp;
                    v0 = v0 * alpha + jb.Hres[(size_t)row * 256 + cin]     * beta;
                    v1 = v1 * alpha + jb.Hres[(size_t)row * 256 + cin + 1] * beta;
                    float2 o; o.x = v0; o.y = v1;
                    *(float2*)(O + (size_t)row * 256 + cin) = o;
                } else {
                    __half* H = (__half*)jb.outp;
                    *(unsigned*)(H + (size_t)row * 256 + cin) = pack2(v0, v1);
                }
            }
        }
    }
}

// ---------------- single-pass CSR scan ----------------
__global__ void scan_kernel() {
    __shared__ int sh[256];
    __shared__ int base;
    int i = blockIdx.x * 256 + threadIdx.x;
    int v = (i < NSEG) ? g_hist[i] : 0;
    sh[threadIdx.x] = v;
    __syncthreads();
    for (int o = 1; o < 256; o <<= 1) {
        int t = (threadIdx.x >= (unsigned)o) ? sh[threadIdx.x - o] : 0;
        __syncthreads();
        sh[threadIdx.x] += t;
        __syncthreads();
    }
    if (threadIdx.x == 255) base = atomicAdd(&g_total, sh[255]);
    __syncthreads();
    int excl = sh[threadIdx.x] - v + base;
    if (i < NSEG) {
        g_rowptr[i] = excl;
        g_cursor[i] = excl;
        g_hist[i] = 0;
    }
}
__global__ void scatter_kernel(const int* __restrict__ s0, const int* __restrict__ d0,
                               const int* __restrict__ s1, const int* __restrict__ d1,
                               const int* __restrict__ s2, const int* __restrict__ d2, int E) {
    int i = blockIdx.x * blockDim.x + threadIdx.x;
    if (i == 0) g_total = 0;
    if (i >= 3 * E) return;
    int r = i / E, e = i - r * E;
    const int* ss = (r == 0) ? s0 : ((r == 1) ? s1 : s2);
    const int* dd = (r == 0) ? d0 : ((r == 1) ? d1 : d2);
    int pos = atomicAdd(&g_cursor[r * N_NODES + dd[e]], 1);
    g_csr[pos] = ss[e];
}

// ---------------- aggregation: warp per (type, dst) ----------------
__global__ void agg_kernel(const float* __restrict__ rel_pri) {
    int gw = (blockIdx.x * blockDim.x + threadIdx.x) >> 5;
    int lane = threadIdx.x & 31;
    if (gw >= 2 * N_NODES) return;
    int t = (gw >= N_NODES) ? 1 : 0;
    int n = gw - t * N_NODES;
    const float rs = 0.17677669529663687f;
    int head = lane >> 2;

    uint4 qu = __ldg((const uint4*)(g_Qh[t] + (size_t)n * DIM + 8 * lane));
    __half2 qh[4] = {*(__half2*)&qu.x, *(__half2*)&qu.y, *(__half2*)&qu.z, *(__half2*)&qu.w};

    float outv[8];
    #pragma unroll
    for (int j = 0; j < 8; j++) outv[j] = 0.f;

    int rfirst = t ? 0 : 1;
    int rcount = t ? 1 : 2;
    float scale = t ? 1.f : 0.5f;

    for (int ri = 0; ri < rcount; ri++) {
        int r = rfirst + ri;
        float pr = rel_pri[r * NHEAD + head] * rs;
        int seg = r * N_NODES + n;
        int beg = g_rowptr[seg], end = g_cursor[seg];
        const __half* Kb = g_kh[r];
        const __half* Vb = g_vh[r];
        float a[8];
        #pragma unroll
        for (int j = 0; j < 8; j++) a[j] = 0.f;
        float ssum = 0.f;
        int i = beg;
        for (; i + 1 < end; i += 2) {
            int sn0 = __ldg(&g_csr[i]), sn1 = __ldg(&g_csr[i + 1]);
            uint4 k0 = __ldg((const uint4*)(Kb + (size_t)sn0 * DIM + 8 * lane));
            uint4 k1 = __ldg((const uint4*)(Kb + (size_t)sn1 * DIM + 8 * lane));
            float v0[8], v1[8];
            ld8h_nc(Vb + (size_t)sn0 * DIM + 8 * lane, v0);
            ld8h_nc(Vb + (size_t)sn1 * DIM + 8 * lane, v1);
            float p0 = dot8h(qh, k0);
            float p1 = dot8h(qh, k1);
            p0 += __shfl_xor_sync(0xffffffffu, p0, 2);
            p1 += __shfl_xor_sync(0xffffffffu, p1, 2);
            p0 += __shfl_xor_sync(0xffffffffu, p0, 1);
            p1 += __shfl_xor_sync(0xffffffffu, p1, 1);
            float ex0 = __expf(p0 * pr);
            float ex1 = __expf(p1 * pr);
            ssum += ex0 + ex1;
            #pragma unroll
            for (int j = 0; j < 8; j++) a[j] += ex0 * v0[j] + ex1 * v1[j];
        }
        if (i < end) {
            int sn = __ldg(&g_csr[i]);
            uint4 kk = __ldg((const uint4*)(Kb + (size_t)sn * DIM + 8 * lane));
            float vv[8];
            ld8h_nc(Vb + (size_t)sn * DIM + 8 * lane, vv);
            float p = dot8h(qh, kk);
            p += __shfl_xor_sync(0xffffffffu, p, 2);
            p += __shfl_xor_sync(0xffffffffu, p, 1);
            float ex = __expf(p * pr);
            ssum += ex;
            #pragma unroll
            for (int j = 0; j < 8; j++) a[j] += ex * vv[j];
        }
        float inv = (ssum > 0.f) ? scale / ssum : 0.f;
        #pragma unroll
        for (int j = 0; j < 8; j++) outv[j] += a[j] * inv;
    }

    // natural-order fp16 write (one uint4)
    uint4 o;
    o.x = pack2(outv[0], outv[1]);
    o.y = pack2(outv[2], outv[3]);
    o.z = pack2(outv[4], outv[5]);
    o.w = pack2(outv[6], outv[7]);
    *(uint4*)(g_tth[t] + (size_t)n * DIM + 8 * lane) = o;
}

// ---------------- launch ----------------
extern "C" void kernel_launch(void* const* d_in, const int* in_sizes, int n_in,
                              void* d_out, int out_size) {
    const float* h_A     = (const float*)d_in[0];
    const float* h_B     = (const float*)d_in[1];
    const float* Wk      = (const float*)d_in[2];
    const float* bk      = (const float*)d_in[3];
    const float* Wq      = (const float*)d_in[4];
    const float* bq      = (const float*)d_in[5];
    const float* Wv      = (const float*)d_in[6];
    const float* bv      = (const float*)d_in[7];
    const float* Wa      = (const float*)d_in[8];
    const float* ba      = (const float*)d_in[9];
    const float* rel_att = (const float*)d_in[10];
    const float* rel_msg = (const float*)d_in[11];
    const float* rel_pri = (const float*)d_in[12];
    const float* skip    = (const float*)d_in[13];
    const int*   src[3]  = {(const int*)d_in[14], (const int*)d_in[16], (const int*)d_in[18]};
    const int*   dst[3]  = {(const int*)d_in[15], (const int*)d_in[17], (const int*)d_in[19]};
    const int E = in_sizes[14];
    float* out = (float*)d_out;

    __half *pHr[2], *pQh[2], *pkh[3], *pvh[3], *pWTh, *pWaTh, *ptt[2];
    float *pbc;
    {
        void* base;
        cudaGetSymbolAddress(&base, g_hrh);  pHr[0] = (__half*)base; pHr[1] = (__half*)base + NODE_F + PAD_F;
        cudaGetSymbolAddress(&base, g_Qh);   pQh[0] = (__half*)base; pQh[1] = (__half*)base + NODE_F;
        cudaGetSymbolAddress(&base, g_kh);   for (int r = 0; r < 3; r++) pkh[r] = (__half*)base + (size_t)r * NODE_F;
        cudaGetSymbolAddress(&base, g_vh);   for (int r = 0; r < 3; r++) pvh[r] = (__half*)base + (size_t)r * NODE_F;
        cudaGetSymbolAddress(&base, g_WTh);  pWTh = (__half*)base;
        cudaGetSymbolAddress(&base, g_bc);   pbc = (float*)base;
        cudaGetSymbolAddress(&base, g_WaTh); pWaTh = (__half*)base;
        cudaGetSymbolAddress(&base, g_tth);  ptt[0] = (__half*)base; ptt[1] = (__half*)base + NODE_F + PAD_F;
    }

    cudaFuncSetAttribute(tgemm, cudaFuncAttributeMaxDynamicSharedMemorySize, TG_SMEM);

    // prep (round + weight build + dst histogram, merged)
    {
        int tot = PREP_BASE + 3 * E;
        prep_kernel<<<(tot + 255) / 256, 256>>>(h_A, h_B, Wq, bq, Wk, bk, Wv, bv, Wa,
                                                rel_att, rel_msg, dst[0], dst[1], dst[2], E);
    }

    // single-pass CSR scan + scatter
    scan_kernel<<<(NSEG + 255) / 256, 256>>>();
    scatter_kernel<<<(3 * E + 255) / 256, 256>>>(src[0], dst[0], src[1], dst[1], src[2], dst[2], E);

    int mblocks = (N_NODES + 127) / 128;

    // merged projection GEMMs: 16 column-tiles -> fp16 outputs
    {
        Jobs jobs;
        __half* targA[5] = {pQh[0], pkh[0], pvh[0], pkh[2], pvh[2]};
        __half* targB[3] = {pQh[1], pkh[1], pvh[1]};
        for (int x = 0; x < 10; x++) {
            int col0 = x * 128;
            jobs.j[x] = { pHr[0], pWTh + (size_t)col0 * 256, pbc + col0,
                          (void*)targA[x >> 1], nullptr, nullptr, (x & 1) * 128, 0 };
        }
        for (int x2 = 0; x2 < 6; x2++) {
            int col0 = 1280 + x2 * 128;
            jobs.j[10 + x2] = { pHr[1], pWTh + (size_t)col0 * 256, pbc + col0,
                                (void*)targB[x2 >> 1], nullptr, nullptr, (x2 & 1) * 128, 0 };
        }
        dim3 grid(16, mblocks);
        tgemm<<<grid, 256, TG_SMEM>>>(jobs, N_NODES);
    }

    // warp-per-(type,dst) aggregation, writes g_tth directly
    {
        int nwarp_blocks = (2 * N_NODES * 32 + 255) / 256;
        agg_kernel<<<nwarp_blocks, 256>>>(rel_pri);
    }

    // merged output GEMMs with fused skip epilogue (f32 out)
    {
        Jobs jobs;
        for (int x = 0; x < 2; x++)
            jobs.j[x] = { ptt[0], pWaTh + (size_t)x * 128 * 256, ba + x * 128,
                          (void*)out, h_A, skip, x * 128, 1 };
        for (int x = 0; x < 2; x++)
            jobs.j[2 + x] = { ptt[1], pWaTh + 65536 + (size_t)x * 128 * 256, ba + 256 + x * 128,
                              (void*)(out + NODE_F), h_B, skip + 1, x * 128, 1 };
        dim3 grid(4, mblocks);
        tgemm<<<grid, 256, TG_SMEM>>>(jobs, N_NODES);
    }
}

// round 15
// speedup vs baseline: 1.0044x; 1.0044x over previous
#include <cuda_runtime.h>
#include <cuda_fp16.h>
#include <math.h>

#define N_NODES 40000
#define E_EDGES 200000
#define DIM 256
#define NHEAD 8
#define NODE_F (N_NODES * DIM)
#define PAD_F (64 * DIM)
#define NSEG (3 * N_NODES)

// ---------------- scratch (device globals) ----------------
__device__ __half g_hrh[2][NODE_F + PAD_F];   // fp16, k-permuted copies of h_A, h_B
__device__ __half g_Qh[2][NODE_F];
__device__ __half g_kh[3][NODE_F];
__device__ __half g_vh[3][NODE_F];
__device__ __half g_WTh[2048 * 256];          // K-major concat weights, fp16, k-permuted
__device__ float  g_bc[2048];
__device__ __half g_WaTh[2 * 256 * 256];      // Wa^T, K-major, fp16, k-permuted
__device__ __half g_tth[2][NODE_F + PAD_F];   // combined features, fp16, k-permuted
__device__ int    g_hist[NSEG];               // zero at load; scan re-zeroes each run
__device__ int    g_rowptr[NSEG];
__device__ int    g_cursor[NSEG];             // after scatter: cursor[seg] == segment end
__device__ int    g_total;                    // zero at load; scatter re-zeroes each run
__device__ int    g_csr[3 * E_EDGES];

struct Job {
    const __half* A; const __half* W; const float* bias; void* outp;
    const float* Hres; const float* skipv; int cin; int mode;
};
struct Jobs { Job j[16]; };

// ---------------- helpers ----------------
__device__ __forceinline__ unsigned pack2(float a, float b) {
    __half2 h = __floats2half2_rn(a, b);
    return *(unsigned*)&h;
}
__device__ __forceinline__ void mma_f16(float* d, const unsigned* a, const unsigned* b) {
    asm volatile(
        "mma.sync.aligned.m16n8k16.row.col.f32.f16.f16.f32 "
        "{%0,%1,%2,%3}, {%4,%5,%6,%7}, {%8,%9}, {%0,%1,%2,%3};"
        : "+f"(d[0]), "+f"(d[1]), "+f"(d[2]), "+f"(d[3])
        : "r"(a[0]), "r"(a[1]), "r"(a[2]), "r"(a[3]), "r"(b[0]), "r"(b[1]));
}
__device__ __forceinline__ void cpa16(unsigned saddr, const void* g) {
    asm volatile("cp.async.cg.shared.global [%0], [%1], 16;" :: "r"(saddr), "l"(g));
}
__device__ __forceinline__ void cpa16_ca(unsigned saddr, const void* g) {
    asm volatile("cp.async.ca.shared.global [%0], [%1], 16;" :: "r"(saddr), "l"(g));
}
__device__ __forceinline__ unsigned smem_u32(const void* p) {
    unsigned a;
    asm("{ .reg .u64 t; cvta.to.shared.u64 t, %1; cvt.u32.u64 %0, t; }" : "=r"(a) : "l"(p));
    return a;
}
__device__ __forceinline__ void ld8h_nc(const __half* p, float* f) {
    uint4 u = __ldg((const uint4*)p);
    float2 a;
    a = __half22float2(*(__half2*)&u.x); f[0] = a.x; f[1] = a.y;
    a = __half22float2(*(__half2*)&u.y); f[2] = a.x; f[3] = a.y;
    a = __half22float2(*(__half2*)&u.z); f[4] = a.x; f[5] = a.y;
    a = __half22float2(*(__half2*)&u.w); f[6] = a.x; f[7] = a.y;
}
__device__ __forceinline__ float dot8h(const __half2* qh, uint4 ku) {
    __half2 acc = __hmul2(qh[0], *(__half2*)&ku.x);
    acc = __hfma2(qh[1], *(__half2*)&ku.y, acc);
    acc = __hfma2(qh[2], *(__half2*)&ku.z, acc);
    acc = __hfma2(qh[3], *(__half2*)&ku.w, acc);
    float2 f = __half22float2(acc);
    return f.x + f.y;
}

// ---------------- prep: round inputs + build weights/biases + dst histogram ----------------
#define NGRP  (NODE_F / 16)
#define TOTW  (2048 * 256)
#define TOTB  2048
#define TOTWA (2 * 256 * 256)
#define PREP_BASE (NGRP + TOTW + TOTB + TOTWA)
__device__ __forceinline__ int halfidx(int k) {
    int w = k >> 1, h = k & 1, wi = w & 7;
    int pw = (wi < 4) ? 2 * wi : 2 * wi - 7;
    return ((w >> 3) << 4) + pw * 2 + h;
}
__global__ void prep_kernel(const float* __restrict__ hA, const float* __restrict__ hB,
                            const float* __restrict__ Wq, const float* __restrict__ bq,
                            const float* __restrict__ Wk, const float* __restrict__ bk,
                            const float* __restrict__ Wv, const float* __restrict__ bv,
                            const float* __restrict__ Wa,
                            const float* __restrict__ rel_att, const float* __restrict__ rel_msg,
                            const int* __restrict__ d0, const int* __restrict__ d1,
                            const int* __restrict__ d2, int E) {
    int gid = blockIdx.x * blockDim.x + threadIdx.x;
    if (gid < NGRP) {
        int i = gid;
        #pragma unroll
        for (int t = 0; t < 2; t++) {
            const float* src = t ? hB : hA;
            float4 f0 = ((const float4*)src)[4 * i + 0];
            float4 f1 = ((const float4*)src)[4 * i + 1];
            float4 f2 = ((const float4*)src)[4 * i + 2];
            float4 f3 = ((const float4*)src)[4 * i + 3];
            unsigned W0 = pack2(f0.x, f0.y), W1 = pack2(f0.z, f0.w);
            unsigned W2 = pack2(f1.x, f1.y), W3 = pack2(f1.z, f1.w);
            unsigned W4 = pack2(f2.x, f2.y), W5 = pack2(f2.z, f2.w);
            unsigned W6 = pack2(f3.x, f3.y), W7 = pack2(f3.z, f3.w);
            ((uint4*)g_hrh[t])[2 * i]     = make_uint4(W0, W4, W1, W5);
            ((uint4*)g_hrh[t])[2 * i + 1] = make_uint4(W2, W6, W3, W7);
        }
        return;
    }
    gid -= NGRP;
    if (gid < TOTW) {
        int k = gid & 255;
        int n = gid >> 8;
        int side  = (n < 1280) ? 0 : 1;
        int local = side ? (n - 1280) : n;
        int g = local >> 8, col = local & 255;
        float val;
        if (g == 0) {
            val = Wq[side * 65536 + k * 256 + col];
        } else {
            int r   = side ? 1 : ((g <= 2) ? 0 : 2);
            int isv = side ? (g == 2) : ((g & 1) == 0);
            const float* W  = (isv ? Wv : Wk) + side * 65536 + k * 256 + (col >> 5) * 32;
            const float* rp = (isv ? rel_msg : rel_att) + r * 8192 + (col >> 5) * 1024 + (col & 31);
            float acc = 0.f;
            #pragma unroll
            for (int d = 0; d < 32; d++) acc += W[d] * rp[d * 32];
            val = acc;
        }
        g_WTh[n * 256 + halfidx(k)] = __float2half_rn(val);
        return;
    }
    gid -= TOTW;
    if (gid < TOTB) {
        int n = gid;
        int side  = (n < 1280) ? 0 : 1;
        int local = side ? (n - 1280) : n;
        int g = local >> 8, col = local & 255;
        float val;
        if (g == 0) {
            val = bq[side * 256 + col];
        } else {
            int r   = side ? 1 : ((g <= 2) ? 0 : 2);
            int isv = side ? (g == 2) : ((g & 1) == 0);
            const float* b  = (isv ? bv : bk) + side * 256 + (col >> 5) * 32;
            const float* rp = (isv ? rel_msg : rel_att) + r * 8192 + (col >> 5) * 1024 + (col & 31);
            float acc = 0.f;
            #pragma unroll
            for (int d = 0; d < 32; d++) acc += b[d] * rp[d * 32];
            val = acc;
        }
        g_bc[n] = val;
        return;
    }
    gid -= TOTB;
    if (gid < TOTWA) {
        int i = gid;
        int k = i & 255, nn = (i >> 8) & 255, t = i >> 16;
        g_WaTh[t * 65536 + nn * 256 + halfidx(k)] = __float2half_rn(Wa[t * 65536 + k * 256 + nn]);
        return;
    }
    gid -= TOTWA;
    if (gid < 3 * E) {
        int r = gid / E, e = gid - r * E;
        const int* dd = (r == 0) ? d0 : ((r == 1) ? d1 : d2);
        atomicAdd(&g_hist[r * N_NODES + dd[e]], 1);
    }
}

// ---------------- fp16 mma.sync GEMM, cp.async 2-stage, K-chunks of 64 halves ----------------
#define SSTR32 40
#define STG_WORDS 10240
#define STG_BYTES 40960u
#define TG_SMEM 81920
__global__ void __launch_bounds__(256, 2) tgemm(Jobs jobs, int M) {
    extern __shared__ float smem[];
    unsigned sbase = smem_u32(smem);
    Job jb = jobs.j[blockIdx.x];
    int tid = threadIdx.x, lane = tid & 31, wid = tid >> 5;
    int row0 = blockIdx.y * 128;
    int wm = (wid >> 2) * 64;
    int wn = (wid & 3) * 32;
    int g = lane >> 2, c = lane & 3;

    float acc[4][4][4];
    #pragma unroll
    for (int i = 0; i < 4; i++)
        #pragma unroll
        for (int j = 0; j < 4; j++)
            #pragma unroll
            for (int q = 0; q < 4; q++) acc[i][j][q] = 0.f;

    int r_st[4], jc_st[4];
    #pragma unroll
    for (int i = 0; i < 4; i++) {
        int sl = i * 256 + tid;
        r_st[i] = sl >> 3; jc_st[i] = sl & 7;
    }

    #pragma unroll
    for (int i = 0; i < 4; i++) {
        unsigned so = sbase + (unsigned)(r_st[i] * 160 + jc_st[i] * 16);
        cpa16(so, jb.A + (size_t)(row0 + r_st[i]) * 256 + jc_st[i] * 8);
        cpa16_ca(so + 20480u, jb.W + (size_t)r_st[i] * 256 + jc_st[i] * 8);
    }
    asm volatile("cp.async.commit_group;" ::: "memory");

    #pragma unroll
    for (int ck = 0; ck < 4; ck++) {
        asm volatile("cp.async.wait_group 0;" ::: "memory");
        __syncthreads();
        if (ck + 1 < 4) {
            unsigned stb = sbase + ((ck + 1) & 1) * STG_BYTES;
            #pragma unroll
            for (int i = 0; i < 4; i++) {
                unsigned so = stb + (unsigned)(r_st[i] * 160 + jc_st[i] * 16);
                cpa16(so, jb.A + (size_t)(row0 + r_st[i]) * 256 + (ck + 1) * 64 + jc_st[i] * 8);
                cpa16_ca(so + 20480u, jb.W + (size_t)r_st[i] * 256 + (ck + 1) * 64 + jc_st[i] * 8);
            }
            asm volatile("cp.async.commit_group;" ::: "memory");
        }
        const unsigned* sAw = ((const unsigned*)smem) + (ck & 1) * STG_WORDS;
        const unsigned* sBw = sAw + 5120;
        #pragma unroll
        for (int s = 0; s < 4; s++) {
            unsigned af[4][4], bf[4][2];
            int kc = s * 8 + 2 * c;
            #pragma unroll
            for (int mt = 0; mt < 4; mt++) {
                int m = wm + mt * 16;
                uint2 lo = *(const uint2*)&sAw[(m + g)     * SSTR32 + kc];
                uint2 hi = *(const uint2*)&sAw[(m + g + 8) * SSTR32 + kc];
                af[mt][0] = lo.x; af[mt][1] = hi.x; af[mt][2] = lo.y; af[mt][3] = hi.y;
            }
            #pragma unroll
            for (int nt = 0; nt < 4; nt++) {
                uint2 b = *(const uint2*)&sBw[(wn + nt * 8 + g) * SSTR32 + kc];
                bf[nt][0] = b.x; bf[nt][1] = b.y;
            }
            #pragma unroll
            for (int mt = 0; mt < 4; mt++)
                #pragma unroll
                for (int nt = 0; nt < 4; nt++)
                    mma_f16(acc[mt][nt], af[mt], bf[nt]);
        }
    }

    float alpha = 1.f, beta = 0.f;
    if (jb.mode == 1) {
        float sv = *jb.skipv;
        alpha = 1.f / (1.f + __expf(-sv));
        beta  = 1.f - alpha;
    }
    int cinb = jb.cin + wn;
    #pragma unroll
    for (int mt = 0; mt < 4; mt++) {
        #pragma unroll
        for (int half = 0; half < 2; half++) {
            int row = row0 + wm + mt * 16 + g + half * 8;
            if (row >= M) continue;
            #pragma unroll
            for (int nt = 0; nt < 4; nt++) {
                int lcol = wn + nt * 8 + 2 * c;
                int cin = cinb + nt * 8 + 2 * c;
                float v0 = acc[mt][nt][half * 2 + 0] + jb.bias[lcol];
                float v1 = acc[mt][nt][half * 2 + 1] + jb.bias[lcol + 1];
                if (jb.mode == 1) {
                    float* O = (float*)jb.outp;
                    v0 = v0 * alpha + jb.Hres[(size_t)row * 256 + cin]     * beta;
                    v1 = v1 * alpha + jb.Hres[(size_t)row * 256 + cin + 1] * beta;
                    float2 o; o.x = v0; o.y = v1;
                    *(float2*)(O + (size_t)row * 256 + cin) = o;
                } else {
                    __half* H = (__half*)jb.outp;
                    *(unsigned*)(H + (size_t)row * 256 + cin) = pack2(v0, v1);
                }
            }
        }
    }
}

// ---------------- single-pass CSR scan ----------------
__global__ void scan_kernel() {
    __shared__ int sh[256];
    __shared__ int base;
    int i = blockIdx.x * 256 + threadIdx.x;
    int v = (i < NSEG) ? g_hist[i] : 0;
    sh[threadIdx.x] = v;
    __syncthreads();
    for (int o = 1; o < 256; o <<= 1) {
        int t = (threadIdx.x >= (unsigned)o) ? sh[threadIdx.x - o] : 0;
        __syncthreads();
        sh[threadIdx.x] += t;
        __syncthreads();
    }
    if (threadIdx.x == 255) base = atomicAdd(&g_total, sh[255]);
    __syncthreads();
    int excl = sh[threadIdx.x] - v + base;
    if (i < NSEG) {
        g_rowptr[i] = excl;
        g_cursor[i] = excl;
        g_hist[i] = 0;
    }
}
__global__ void scatter_kernel(const int* __restrict__ s0, const int* __restrict__ d0,
                               const int* __restrict__ s1, const int* __restrict__ d1,
                               const int* __restrict__ s2, const int* __restrict__ d2, int E) {
    int i = blockIdx.x * blockDim.x + threadIdx.x;
    if (i == 0) g_total = 0;
    if (i >= 3 * E) return;
    int r = i / E, e = i - r * E;
    const int* ss = (r == 0) ? s0 : ((r == 1) ? s1 : s2);
    const int* dd = (r == 0) ? d0 : ((r == 1) ? d1 : d2);
    int pos = atomicAdd(&g_cursor[r * N_NODES + dd[e]], 1);
    g_csr[pos] = ss[e];
}

// ---------------- aggregation: warp per (type, dst) ----------------
__global__ void agg_kernel(const float* __restrict__ rel_pri) {
    int gw = (blockIdx.x * blockDim.x + threadIdx.x) >> 5;
    int lane = threadIdx.x & 31;
    if (gw >= 2 * N_NODES) return;
    int t = (gw >= N_NODES) ? 1 : 0;
    int n = gw - t * N_NODES;
    const float rs = 0.17677669529663687f;
    int head = lane >> 2;

    uint4 qu = __ldg((const uint4*)(g_Qh[t] + (size_t)n * DIM + 8 * lane));
    __half2 qh[4] = {*(__half2*)&qu.x, *(__half2*)&qu.y, *(__half2*)&qu.z, *(__half2*)&qu.w};

    float outv[8];
    #pragma unroll
    for (int j = 0; j < 8; j++) outv[j] = 0.f;

    int rfirst = t ? 0 : 1;
    int rcount = t ? 1 : 2;
    float scale = t ? 1.f : 0.5f;

    for (int ri = 0; ri < rcount; ri++) {
        int r = rfirst + ri;
        float pr = rel_pri[r * NHEAD + head] * rs;
        int seg = r * N_NODES + n;
        int beg = g_rowptr[seg], end = g_cursor[seg];
        const __half* Kb = g_kh[r];
        const __half* Vb = g_vh[r];
        float a[8];
        #pragma unroll
        for (int j = 0; j < 8; j++) a[j] = 0.f;
        float ssum = 0.f;
        int i = beg;
        for (; i + 1 < end; i += 2) {
            int sn0 = __ldg(&g_csr[i]), sn1 = __ldg(&g_csr[i + 1]);
            uint4 k0 = __ldg((const uint4*)(Kb + (size_t)sn0 * DIM + 8 * lane));
            uint4 k1 = __ldg((const uint4*)(Kb + (size_t)sn1 * DIM + 8 * lane));
            float v0[8], v1[8];
            ld8h_nc(Vb + (size_t)sn0 * DIM + 8 * lane, v0);
            ld8h_nc(Vb + (size_t)sn1 * DIM + 8 * lane, v1);
            float p0 = dot8h(qh, k0);
            float p1 = dot8h(qh, k1);
            p0 += __shfl_xor_sync(0xffffffffu, p0, 2);
            p1 += __shfl_xor_sync(0xffffffffu, p1, 2);
            p0 += __shfl_xor_sync(0xffffffffu, p0, 1);
            p1 += __shfl_xor_sync(0xffffffffu, p1, 1);
            float ex0 = __expf(p0 * pr);
            float ex1 = __expf(p1 * pr);
            ssum += ex0 + ex1;
            #pragma unroll
            for (int j = 0; j < 8; j++) a[j] += ex0 * v0[j] + ex1 * v1[j];
        }
        if (i < end) {
            int sn = __ldg(&g_csr[i]);
            uint4 kk = __ldg((const uint4*)(Kb + (size_t)sn * DIM + 8 * lane));
            float vv[8];
            ld8h_nc(Vb + (size_t)sn * DIM + 8 * lane, vv);
            float p = dot8h(qh, kk);
            p += __shfl_xor_sync(0xffffffffu, p, 2);
            p += __shfl_xor_sync(0xffffffffu, p, 1);
            float ex = __expf(p * pr);
            ssum += ex;
            #pragma unroll
            for (int j = 0; j < 8; j++) a[j] += ex * vv[j];
        }
        float inv = (ssum > 0.f) ? scale / ssum : 0.f;
        #pragma unroll
        for (int j = 0; j < 8; j++) outv[j] += a[j] * inv;
    }

    unsigned* orow = (unsigned*)(g_tth[t] + (size_t)n * DIM);
    #pragma unroll
    for (int j = 0; j < 4; j++) {
        int w = 4 * lane + j;
        int wi = w & 7;
        int pos = (w & ~7) + ((wi < 4) ? 2 * wi : 2 * wi - 7);
        orow[pos] = pack2(outv[2 * j], outv[2 * j + 1]);
    }
}

// ---------------- launch ----------------
extern "C" void kernel_launch(void* const* d_in, const int* in_sizes, int n_in,
                              void* d_out, int out_size) {
    const float* h_A     = (const float*)d_in[0];
    const float* h_B     = (const float*)d_in[1];
    const float* Wk      = (const float*)d_in[2];
    const float* bk      = (const float*)d_in[3];
    const float* Wq      = (const float*)d_in[4];
    const float* bq      = (const float*)d_in[5];
    const float* Wv      = (const float*)d_in[6];
    const float* bv      = (const float*)d_in[7];
    const float* Wa      = (const float*)d_in[8];
    const float* ba      = (const float*)d_in[9];
    const float* rel_att = (const float*)d_in[10];
    const float* rel_msg = (const float*)d_in[11];
    const float* rel_pri = (const float*)d_in[12];
    const float* skip    = (const float*)d_in[13];
    const int*   src[3]  = {(const int*)d_in[14], (const int*)d_in[16], (const int*)d_in[18]};
    const int*   dst[3]  = {(const int*)d_in[15], (const int*)d_in[17], (const int*)d_in[19]};
    const int E = in_sizes[14];
    float* out = (float*)d_out;

    __half *pHr[2], *pQh[2], *pkh[3], *pvh[3], *pWTh, *pWaTh, *ptt[2];
    float *pbc;
    {
        void* base;
        cudaGetSymbolAddress(&base, g_hrh);  pHr[0] = (__half*)base; pHr[1] = (__half*)base + NODE_F + PAD_F;
        cudaGetSymbolAddress(&base, g_Qh);   pQh[0] = (__half*)base; pQh[1] = (__half*)base + NODE_F;
        cudaGetSymbolAddress(&base, g_kh);   for (int r = 0; r < 3; r++) pkh[r] = (__half*)base + (size_t)r * NODE_F;
        cudaGetSymbolAddress(&base, g_vh);   for (int r = 0; r < 3; r++) pvh[r] = (__half*)base + (size_t)r * NODE_F;
        cudaGetSymbolAddress(&base, g_WTh);  pWTh = (__half*)base;
        cudaGetSymbolAddress(&base, g_bc);   pbc = (float*)base;
        cudaGetSymbolAddress(&base, g_WaTh); pWaTh = (__half*)base;
        cudaGetSymbolAddress(&base, g_tth);  ptt[0] = (__half*)base; ptt[1] = (__half*)base + NODE_F + PAD_F;
    }

    cudaFuncSetAttribute(tgemm, cudaFuncAttributeMaxDynamicSharedMemorySize, TG_SMEM);

    // prep (round + weight build + dst histogram, merged)
    {
        int tot = PREP_BASE + 3 * E;
        prep_kernel<<<(tot + 255) / 256, 256>>>(h_A, h_B, Wq, bq, Wk, bk, Wv, bv, Wa,
                                                rel_att, rel_msg, dst[0], dst[1], dst[2], E);
    }

    // single-pass CSR scan + scatter
    scan_kernel<<<(NSEG + 255) / 256, 256>>>();
    scatter_kernel<<<(3 * E + 255) / 256, 256>>>(src[0], dst[0], src[1], dst[1], src[2], dst[2], E);

    int mblocks = (N_NODES + 127) / 128;

    // merged projection GEMMs: 16 column-tiles -> fp16 outputs
    {
        Jobs jobs;
        __half* targA[5] = {pQh[0], pkh[0], pvh[0], pkh[2], pvh[2]};
        __half* targB[3] = {pQh[1], pkh[1], pvh[1]};
        for (int x = 0; x < 10; x++) {
            int col0 = x * 128;
            jobs.j[x] = { pHr[0], pWTh + (size_t)col0 * 256, pbc + col0,
                          (void*)targA[x >> 1], nullptr, nullptr, (x & 1) * 128, 0 };
        }
        for (int x2 = 0; x2 < 6; x2++) {
            int col0 = 1280 + x2 * 128;
            jobs.j[10 + x2] = { pHr[1], pWTh + (size_t)col0 * 256, pbc + col0,
                                (void*)targB[x2 >> 1], nullptr, nullptr, (x2 & 1) * 128, 0 };
        }
        dim3 grid(16, mblocks);
        tgemm<<<grid, 256, TG_SMEM>>>(jobs, N_NODES);
    }

    // warp-per-(type,dst) aggregation, writes g_tth directly
    {
        int nwarp_blocks = (2 * N_NODES * 32 + 255) / 256;
        agg_kernel<<<nwarp_blocks, 256>>>(rel_pri);
    }

    // merged output GEMMs with fused skip epilogue (f32 out)
    {
        Jobs jobs;
        for (int x = 0; x < 2; x++)
            jobs.j[x] = { ptt[0], pWaTh + (size_t)x * 128 * 256, ba + x * 128,
                          (void*)out, h_A, skip, x * 128, 1 };
        for (int x = 0; x < 2; x++)
            jobs.j[2 + x] = { ptt[1], pWaTh + 65536 + (size_t)x * 128 * 256, ba + 256 + x * 128,
                              (void*)(out + NODE_F), h_B, skip + 1, x * 128, 1 };
        dim3 grid(4, mblocks);
        tgemm<<<grid, 256, TG_SMEM>>>(jobs, N_NODES);
    }
}

// round 16
// speedup vs baseline: 1.0138x; 1.0094x over previous
#include <cuda_runtime.h>
#include <cuda_fp16.h>
#include <math.h>

#define N_NODES 40000
#define E_EDGES 200000
#define DIM 256
#define NHEAD 8
#define NODE_F (N_NODES * DIM)
#define PAD_F (64 * DIM)
#define NSEG (3 * N_NODES)

// ---------------- scratch (device globals) ----------------
__device__ __half g_hrh[2][NODE_F + PAD_F];   // fp16, k-permuted copies of h_A, h_B
__device__ __half g_Qh[2][NODE_F];
__device__ __half g_kh[3][NODE_F];
__device__ __half g_vh[3][NODE_F];
__device__ __half g_WTh[2048 * 256];          // K-major concat weights, fp16, k-permuted
__device__ float  g_bc[2048];
__device__ __half g_WaTh[2 * 256 * 256];      // Wa^T, K-major, fp16, k-permuted
__device__ __half g_tth[2][NODE_F + PAD_F];   // combined features, fp16, k-permuted
__device__ int    g_hist[NSEG];               // zero at load; scan re-zeroes each run
__device__ int    g_rowptr[NSEG];
__device__ int    g_cursor[NSEG];             // after scatter: cursor[seg] == segment end
__device__ int    g_total;                    // zero at load; scatter role re-zeroes each run
__device__ int    g_csr[3 * E_EDGES];

struct Job {
    const __half* A; const __half* W; const float* bias; void* outp;
    const float* Hres; const float* skipv; int cin; int mode;
};
struct Jobs { Job j[16]; };

// ---------------- helpers ----------------
__device__ __forceinline__ unsigned pack2(float a, float b) {
    __half2 h = __floats2half2_rn(a, b);
    return *(unsigned*)&h;
}
__device__ __forceinline__ void mma_f16(float* d, const unsigned* a, const unsigned* b) {
    asm volatile(
        "mma.sync.aligned.m16n8k16.row.col.f32.f16.f16.f32 "
        "{%0,%1,%2,%3}, {%4,%5,%6,%7}, {%8,%9}, {%0,%1,%2,%3};"
        : "+f"(d[0]), "+f"(d[1]), "+f"(d[2]), "+f"(d[3])
        : "r"(a[0]), "r"(a[1]), "r"(a[2]), "r"(a[3]), "r"(b[0]), "r"(b[1]));
}
__device__ __forceinline__ void cpa16(unsigned saddr, const void* g) {
    asm volatile("cp.async.cg.shared.global [%0], [%1], 16;" :: "r"(saddr), "l"(g));
}
__device__ __forceinline__ unsigned smem_u32(const void* p) {
    unsigned a;
    asm("{ .reg .u64 t; cvta.to.shared.u64 t, %1; cvt.u32.u64 %0, t; }" : "=r"(a) : "l"(p));
    return a;
}
__device__ __forceinline__ void ld8h_nc(const __half* p, float* f) {
    uint4 u = __ldg((const uint4*)p);
    float2 a;
    a = __half22float2(*(__half2*)&u.x); f[0] = a.x; f[1] = a.y;
    a = __half22float2(*(__half2*)&u.y); f[2] = a.x; f[3] = a.y;
    a = __half22float2(*(__half2*)&u.z); f[4] = a.x; f[5] = a.y;
    a = __half22float2(*(__half2*)&u.w); f[6] = a.x; f[7] = a.y;
}
__device__ __forceinline__ float dot8h(const __half2* qh, uint4 ku) {
    __half2 acc = __hmul2(qh[0], *(__half2*)&ku.x);
    acc = __hfma2(qh[1], *(__half2*)&ku.y, acc);
    acc = __hfma2(qh[2], *(__half2*)&ku.z, acc);
    acc = __hfma2(qh[3], *(__half2*)&ku.w, acc);
    float2 f = __half22float2(acc);
    return f.x + f.y;
}

// ---------------- prep: round inputs + build weights/biases + dst histogram ----------------
#define NGRP  (NODE_F / 16)
#define TOTW  (2048 * 256)
#define TOTB  2048
#define TOTWA (2 * 256 * 256)
#define PREP_BASE (NGRP + TOTW + TOTB + TOTWA)
__device__ __forceinline__ int halfidx(int k) {
    int w = k >> 1, h = k & 1, wi = w & 7;
    int pw = (wi < 4) ? 2 * wi : 2 * wi - 7;
    return ((w >> 3) << 4) + pw * 2 + h;
}
__global__ void prep_kernel(const float* __restrict__ hA, const float* __restrict__ hB,
                            const float* __restrict__ Wq, const float* __restrict__ bq,
                            const float* __restrict__ Wk, const float* __restrict__ bk,
                            const float* __restrict__ Wv, const float* __restrict__ bv,
                            const float* __restrict__ Wa,
                            const float* __restrict__ rel_att, const float* __restrict__ rel_msg,
                            const int* __restrict__ d0, const int* __restrict__ d1,
                            const int* __restrict__ d2, int E) {
    int gid = blockIdx.x * blockDim.x + threadIdx.x;
    if (gid < NGRP) {
        int i = gid;
        #pragma unroll
        for (int t = 0; t < 2; t++) {
            const float* src = t ? hB : hA;
            float4 f0 = ((const float4*)src)[4 * i + 0];
            float4 f1 = ((const float4*)src)[4 * i + 1];
            float4 f2 = ((const float4*)src)[4 * i + 2];
            float4 f3 = ((const float4*)src)[4 * i + 3];
            unsigned W0 = pack2(f0.x, f0.y), W1 = pack2(f0.z, f0.w);
            unsigned W2 = pack2(f1.x, f1.y), W3 = pack2(f1.z, f1.w);
            unsigned W4 = pack2(f2.x, f2.y), W5 = pack2(f2.z, f2.w);
            unsigned W6 = pack2(f3.x, f3.y), W7 = pack2(f3.z, f3.w);
            ((uint4*)g_hrh[t])[2 * i]     = make_uint4(W0, W4, W1, W5);
            ((uint4*)g_hrh[t])[2 * i + 1] = make_uint4(W2, W6, W3, W7);
        }
        return;
    }
    gid -= NGRP;
    if (gid < TOTW) {
        int k = gid & 255;
        int n = gid >> 8;
        int side  = (n < 1280) ? 0 : 1;
        int local = side ? (n - 1280) : n;
        int g = local >> 8, col = local & 255;
        float val;
        if (g == 0) {
            val = Wq[side * 65536 + k * 256 + col];
        } else {
            int r   = side ? 1 : ((g <= 2) ? 0 : 2);
            int isv = side ? (g == 2) : ((g & 1) == 0);
            const float* W  = (isv ? Wv : Wk) + side * 65536 + k * 256 + (col >> 5) * 32;
            const float* rp = (isv ? rel_msg : rel_att) + r * 8192 + (col >> 5) * 1024 + (col & 31);
            float acc = 0.f;
            #pragma unroll
            for (int d = 0; d < 32; d++) acc += W[d] * rp[d * 32];
            val = acc;
        }
        g_WTh[n * 256 + halfidx(k)] = __float2half_rn(val);
        return;
    }
    gid -= TOTW;
    if (gid < TOTB) {
        int n = gid;
        int side  = (n < 1280) ? 0 : 1;
        int local = side ? (n - 1280) : n;
        int g = local >> 8, col = local & 255;
        float val;
        if (g == 0) {
            val = bq[side * 256 + col];
        } else {
            int r   = side ? 1 : ((g <= 2) ? 0 : 2);
            int isv = side ? (g == 2) : ((g & 1) == 0);
            const float* b  = (isv ? bv : bk) + side * 256 + (col >> 5) * 32;
            const float* rp = (isv ? rel_msg : rel_att) + r * 8192 + (col >> 5) * 1024 + (col & 31);
            float acc = 0.f;
            #pragma unroll
            for (int d = 0; d < 32; d++) acc += b[d] * rp[d * 32];
            val = acc;
        }
        g_bc[n] = val;
        return;
    }
    gid -= TOTB;
    if (gid < TOTWA) {
        int i = gid;
        int k = i & 255, nn = (i >> 8) & 255, t = i >> 16;
        g_WaTh[t * 65536 + nn * 256 + halfidx(k)] = __float2half_rn(Wa[t * 65536 + k * 256 + nn]);
        return;
    }
    gid -= TOTWA;
    if (gid < 3 * E) {
        int r = gid / E, e = gid - r * E;
        const int* dd = (r == 0) ? d0 : ((r == 1) ? d1 : d2);
        atomicAdd(&g_hist[r * N_NODES + dd[e]], 1);
    }
}

// ---------------- fp16 mma.sync GEMM (R13 proven) + fused scatter role ----------------
// blocks with blockIdx.x == njobs run the CSR edge scatter instead of GEMM.
#define SSTR32 40
#define STG_WORDS 10240
#define STG_BYTES 40960u
#define TG_SMEM 81920
__global__ void __launch_bounds__(256, 2) tgemm(
        Jobs jobs, int M, int njobs,
        const int* __restrict__ s0, const int* __restrict__ d0,
        const int* __restrict__ s1, const int* __restrict__ d1,
        const int* __restrict__ s2, const int* __restrict__ d2, int E) {
    extern __shared__ float smem[];
    int tid = threadIdx.x;

    if ((int)blockIdx.x == njobs) {
        // scatter role: grid-stride over 3E edges using gridDim.y blocks
        int base = blockIdx.y * 256 + tid;
        int stride = gridDim.y * 256;
        if (base == 0) g_total = 0;            // restore for next graph replay
        for (int i = base; i < 3 * E; i += stride) {
            int r = i / E, e = i - r * E;
            const int* ss = (r == 0) ? s0 : ((r == 1) ? s1 : s2);
            const int* dd = (r == 0) ? d0 : ((r == 1) ? d1 : d2);
            int pos = atomicAdd(&g_cursor[r * N_NODES + dd[e]], 1);
            g_csr[pos] = ss[e];
        }
        return;
    }

    unsigned sbase = smem_u32(smem);
    Job jb = jobs.j[blockIdx.x];
    int lane = tid & 31, wid = tid >> 5;
    int row0 = blockIdx.y * 128;
    int wm = (wid >> 2) * 64;
    int wn = (wid & 3) * 32;
    int g = lane >> 2, c = lane & 3;

    float acc[4][4][4];
    #pragma unroll
    for (int i = 0; i < 4; i++)
        #pragma unroll
        for (int j = 0; j < 4; j++)
            #pragma unroll
            for (int q = 0; q < 4; q++) acc[i][j][q] = 0.f;

    int r_st[4], jc_st[4];
    #pragma unroll
    for (int i = 0; i < 4; i++) {
        int sl = i * 256 + tid;
        r_st[i] = sl >> 3; jc_st[i] = sl & 7;
    }

    #pragma unroll
    for (int i = 0; i < 4; i++) {
        unsigned so = sbase + (unsigned)(r_st[i] * 160 + jc_st[i] * 16);
        cpa16(so, jb.A + (size_t)(row0 + r_st[i]) * 256 + jc_st[i] * 8);
        cpa16(so + 20480u, jb.W + (size_t)r_st[i] * 256 + jc_st[i] * 8);
    }
    asm volatile("cp.async.commit_group;" ::: "memory");

    #pragma unroll
    for (int ck = 0; ck < 4; ck++) {
        asm volatile("cp.async.wait_group 0;" ::: "memory");
        __syncthreads();
        if (ck + 1 < 4) {
            unsigned stb = sbase + ((ck + 1) & 1) * STG_BYTES;
            #pragma unroll
            for (int i = 0; i < 4; i++) {
                unsigned so = stb + (unsigned)(r_st[i] * 160 + jc_st[i] * 16);
                cpa16(so, jb.A + (size_t)(row0 + r_st[i]) * 256 + (ck + 1) * 64 + jc_st[i] * 8);
                cpa16(so + 20480u, jb.W + (size_t)r_st[i] * 256 + (ck + 1) * 64 + jc_st[i] * 8);
            }
            asm volatile("cp.async.commit_group;" ::: "memory");
        }
        const unsigned* sAw = ((const unsigned*)smem) + (ck & 1) * STG_WORDS;
        const unsigned* sBw = sAw + 5120;
        #pragma unroll
        for (int s = 0; s < 4; s++) {
            unsigned af[4][4], bf[4][2];
            int kc = s * 8 + 2 * c;
            #pragma unroll
            for (int mt = 0; mt < 4; mt++) {
                int m = wm + mt * 16;
                uint2 lo = *(const uint2*)&sAw[(m + g)     * SSTR32 + kc];
                uint2 hi = *(const uint2*)&sAw[(m + g + 8) * SSTR32 + kc];
                af[mt][0] = lo.x; af[mt][1] = hi.x; af[mt][2] = lo.y; af[mt][3] = hi.y;
            }
            #pragma unroll
            for (int nt = 0; nt < 4; nt++) {
                uint2 b = *(const uint2*)&sBw[(wn + nt * 8 + g) * SSTR32 + kc];
                bf[nt][0] = b.x; bf[nt][1] = b.y;
            }
            #pragma unroll
            for (int mt = 0; mt < 4; mt++)
                #pragma unroll
                for (int nt = 0; nt < 4; nt++)
                    mma_f16(acc[mt][nt], af[mt], bf[nt]);
        }
    }

    float alpha = 1.f, beta = 0.f;
    if (jb.mode == 1) {
        float sv = *jb.skipv;
        alpha = 1.f / (1.f + __expf(-sv));
        beta  = 1.f - alpha;
    }
    int cinb = jb.cin + wn;
    #pragma unroll
    for (int mt = 0; mt < 4; mt++) {
        #pragma unroll
        for (int half = 0; half < 2; half++) {
            int row = row0 + wm + mt * 16 + g + half * 8;
            if (row >= M) continue;
            #pragma unroll
            for (int nt = 0; nt < 4; nt++) {
                int lcol = wn + nt * 8 + 2 * c;
                int cin = cinb + nt * 8 + 2 * c;
                float v0 = acc[mt][nt][half * 2 + 0] + jb.bias[lcol];
                float v1 = acc[mt][nt][half * 2 + 1] + jb.bias[lcol + 1];
                if (jb.mode == 1) {
                    float* O = (float*)jb.outp;
                    v0 = v0 * alpha + jb.Hres[(size_t)row * 256 + cin]     * beta;
                    v1 = v1 * alpha + jb.Hres[(size_t)row * 256 + cin + 1] * beta;
                    float2 o; o.x = v0; o.y = v1;
                    *(float2*)(O + (size_t)row * 256 + cin) = o;
                } else {
                    __half* H = (__half*)jb.outp;
                    *(unsigned*)(H + (size_t)row * 256 + cin) = pack2(v0, v1);
                }
            }
        }
    }
}

// ---------------- single-pass CSR scan ----------------
__global__ void scan_kernel() {
    __shared__ int sh[256];
    __shared__ int base;
    int i = blockIdx.x * 256 + threadIdx.x;
    int v = (i < NSEG) ? g_hist[i] : 0;
    sh[threadIdx.x] = v;
    __syncthreads();
    for (int o = 1; o < 256; o <<= 1) {
        int t = (threadIdx.x >= (unsigned)o) ? sh[threadIdx.x - o] : 0;
        __syncthreads();
        sh[threadIdx.x] += t;
        __syncthreads();
    }
    if (threadIdx.x == 255) base = atomicAdd(&g_total, sh[255]);
    __syncthreads();
    int excl = sh[threadIdx.x] - v + base;
    if (i < NSEG) {
        g_rowptr[i] = excl;
        g_cursor[i] = excl;
        g_hist[i] = 0;
    }
}

// ---------------- aggregation: warp per (type, dst) ----------------
__global__ void agg_kernel(const float* __restrict__ rel_pri) {
    int gw = (blockIdx.x * blockDim.x + threadIdx.x) >> 5;
    int lane = threadIdx.x & 31;
    if (gw >= 2 * N_NODES) return;
    int t = (gw >= N_NODES) ? 1 : 0;
    int n = gw - t * N_NODES;
    const float rs = 0.17677669529663687f;
    int head = lane >> 2;

    uint4 qu = __ldg((const uint4*)(g_Qh[t] + (size_t)n * DIM + 8 * lane));
    __half2 qh[4] = {*(__half2*)&qu.x, *(__half2*)&qu.y, *(__half2*)&qu.z, *(__half2*)&qu.w};

    float outv[8];
    #pragma unroll
    for (int j = 0; j < 8; j++) outv[j] = 0.f;

    int rfirst = t ? 0 : 1;
    int rcount = t ? 1 : 2;
    float scale = t ? 1.f : 0.5f;

    for (int ri = 0; ri < rcount; ri++) {
        int r = rfirst + ri;
        float pr = rel_pri[r * NHEAD + head] * rs;
        int seg = r * N_NODES + n;
        int beg = g_rowptr[seg], end = g_cursor[seg];
        const __half* Kb = g_kh[r];
        const __half* Vb = g_vh[r];
        float a[8];
        #pragma unroll
        for (int j = 0; j < 8; j++) a[j] = 0.f;
        float ssum = 0.f;
        int i = beg;
        for (; i + 1 < end; i += 2) {
            int sn0 = __ldg(&g_csr[i]), sn1 = __ldg(&g_csr[i + 1]);
            uint4 k0 = __ldg((const uint4*)(Kb + (size_t)sn0 * DIM + 8 * lane));
            uint4 k1 = __ldg((const uint4*)(Kb + (size_t)sn1 * DIM + 8 * lane));
            float v0[8], v1[8];
            ld8h_nc(Vb + (size_t)sn0 * DIM + 8 * lane, v0);
            ld8h_nc(Vb + (size_t)sn1 * DIM + 8 * lane, v1);
            float p0 = dot8h(qh, k0);
            float p1 = dot8h(qh, k1);
            p0 += __shfl_xor_sync(0xffffffffu, p0, 2);
            p1 += __shfl_xor_sync(0xffffffffu, p1, 2);
            p0 += __shfl_xor_sync(0xffffffffu, p0, 1);
            p1 += __shfl_xor_sync(0xffffffffu, p1, 1);
            float ex0 = __expf(p0 * pr);
            float ex1 = __expf(p1 * pr);
            ssum += ex0 + ex1;
            #pragma unroll
            for (int j = 0; j < 8; j++) a[j] += ex0 * v0[j] + ex1 * v1[j];
        }
        if (i < end) {
            int sn = __ldg(&g_csr[i]);
            uint4 kk = __ldg((const uint4*)(Kb + (size_t)sn * DIM + 8 * lane));
            float vv[8];
            ld8h_nc(Vb + (size_t)sn * DIM + 8 * lane, vv);
            float p = dot8h(qh, kk);
            p += __shfl_xor_sync(0xffffffffu, p, 2);
            p += __shfl_xor_sync(0xffffffffu, p, 1);
            float ex = __expf(p * pr);
            ssum += ex;
            #pragma unroll
            for (int j = 0; j < 8; j++) a[j] += ex * vv[j];
        }
        float inv = (ssum > 0.f) ? scale / ssum : 0.f;
        #pragma unroll
        for (int j = 0; j < 8; j++) outv[j] += a[j] * inv;
    }

    unsigned* orow = (unsigned*)(g_tth[t] + (size_t)n * DIM);
    #pragma unroll
    for (int j = 0; j < 4; j++) {
        int w = 4 * lane + j;
        int wi = w & 7;
        int pos = (w & ~7) + ((wi < 4) ? 2 * wi : 2 * wi - 7);
        orow[pos] = pack2(outv[2 * j], outv[2 * j + 1]);
    }
}

// ---------------- launch ----------------
extern "C" void kernel_launch(void* const* d_in, const int* in_sizes, int n_in,
                              void* d_out, int out_size) {
    const float* h_A     = (const float*)d_in[0];
    const float* h_B     = (const float*)d_in[1];
    const float* Wk      = (const float*)d_in[2];
    const float* bk      = (const float*)d_in[3];
    const float* Wq      = (const float*)d_in[4];
    const float* bq      = (const float*)d_in[5];
    const float* Wv      = (const float*)d_in[6];
    const float* bv      = (const float*)d_in[7];
    const float* Wa      = (const float*)d_in[8];
    const float* ba      = (const float*)d_in[9];
    const float* rel_att = (const float*)d_in[10];
    const float* rel_msg = (const float*)d_in[11];
    const float* rel_pri = (const float*)d_in[12];
    const float* skip    = (const float*)d_in[13];
    const int*   src[3]  = {(const int*)d_in[14], (const int*)d_in[16], (const int*)d_in[18]};
    const int*   dst[3]  = {(const int*)d_in[15], (const int*)d_in[17], (const int*)d_in[19]};
    const int E = in_sizes[14];
    float* out = (float*)d_out;

    __half *pHr[2], *pQh[2], *pkh[3], *pvh[3], *pWTh, *pWaTh, *ptt[2];
    float *pbc;
    {
        void* base;
        cudaGetSymbolAddress(&base, g_hrh);  pHr[0] = (__half*)base; pHr[1] = (__half*)base + NODE_F + PAD_F;
        cudaGetSymbolAddress(&base, g_Qh);   pQh[0] = (__half*)base; pQh[1] = (__half*)base + NODE_F;
        cudaGetSymbolAddress(&base, g_kh);   for (int r = 0; r < 3; r++) pkh[r] = (__half*)base + (size_t)r * NODE_F;
        cudaGetSymbolAddress(&base, g_vh);   for (int r = 0; r < 3; r++) pvh[r] = (__half*)base + (size_t)r * NODE_F;
        cudaGetSymbolAddress(&base, g_WTh);  pWTh = (__half*)base;
        cudaGetSymbolAddress(&base, g_bc);   pbc = (float*)base;
        cudaGetSymbolAddress(&base, g_WaTh); pWaTh = (__half*)base;
        cudaGetSymbolAddress(&base, g_tth);  ptt[0] = (__half*)base; ptt[1] = (__half*)base + NODE_F + PAD_F;
    }

    cudaFuncSetAttribute(tgemm, cudaFuncAttributeMaxDynamicSharedMemorySize, TG_SMEM);

    // prep (round + weight build + dst histogram, merged)
    {
        int tot = PREP_BASE + 3 * E;
        prep_kernel<<<(tot + 255) / 256, 256>>>(h_A, h_B, Wq, bq, Wk, bk, Wv, bv, Wa,
                                                rel_att, rel_msg, dst[0], dst[1], dst[2], E);
    }

    // single-pass CSR scan
    scan_kernel<<<(NSEG + 255) / 256, 256>>>();

    int mblocks = (N_NODES + 127) / 128;

    // merged projection GEMMs (16 col-tiles) + fused edge scatter (blockIdx.x==16)
    {
        Jobs jobs;
        __half* targA[5] = {pQh[0], pkh[0], pvh[0], pkh[2], pvh[2]};
        __half* targB[3] = {pQh[1], pkh[1], pvh[1]};
        for (int x = 0; x < 10; x++) {
            int col0 = x * 128;
            jobs.j[x] = { pHr[0], pWTh + (size_t)col0 * 256, pbc + col0,
                          (void*)targA[x >> 1], nullptr, nullptr, (x & 1) * 128, 0 };
        }
        for (int x2 = 0; x2 < 6; x2++) {
            int col0 = 1280 + x2 * 128;
            jobs.j[10 + x2] = { pHr[1], pWTh + (size_t)col0 * 256, pbc + col0,
                                (void*)targB[x2 >> 1], nullptr, nullptr, (x2 & 1) * 128, 0 };
        }
        dim3 grid(17, mblocks);
        tgemm<<<grid, 256, TG_SMEM>>>(jobs, N_NODES, 16,
                                      src[0], dst[0], src[1], dst[1], src[2], dst[2], E);
    }

    // warp-per-(type,dst) aggregation, writes g_tth directly
    {
        int nwarp_blocks = (2 * N_NODES * 32 + 255) / 256;
        agg_kernel<<<nwarp_blocks, 256>>>(rel_pri);
    }

    // merged output GEMMs with fused skip epilogue (f32 out); no scatter role (njobs=5 > grid.x-1)
    {
        Jobs jobs;
        for (int x = 0; x < 2; x++)
            jobs.j[x] = { ptt[0], pWaTh + (size_t)x * 128 * 256, ba + x * 128,
                          (void*)out, h_A, skip, x * 128, 1 };
        for (int x = 0; x < 2; x++)
            jobs.j[2 + x] = { ptt[1], pWaTh + 65536 + (size_t)x * 128 * 256, ba + 256 + x * 128,
                              (void*)(out + NODE_F), h_B, skip + 1, x * 128, 1 };
        dim3 grid(4, mblocks);
        tgemm<<<grid, 256, TG_SMEM>>>(jobs, N_NODES, 5,
                                      src[0], dst[0], src[1], dst[1], src[2], dst[2], E);
    }
}

// round 17
// speedup vs baseline: 1.0301x; 1.0161x over previous
#include <cuda_runtime.h>
#include <cuda_fp16.h>
#include <math.h>

#define N_NODES 40000
#define E_EDGES 200000
#define DIM 256
#define NHEAD 8
#define NODE_F (N_NODES * DIM)
#define PAD_F (64 * DIM)
#define NSEG (3 * N_NODES)

// ---------------- scratch (device globals) ----------------
__device__ __half g_hrh[2][NODE_F + PAD_F];   // fp16, k-permuted copies of h_A, h_B
__device__ __half g_Qh[2][NODE_F];
__device__ __half g_kh[3][NODE_F];
__device__ __half g_vh[3][NODE_F];
__device__ __half g_WTh[2048 * 256];          // K-major concat weights, fp16, k-permuted
__device__ float  g_bc[2048];
__device__ __half g_WaTh[2 * 256 * 256];      // Wa^T, K-major, fp16, k-permuted
__device__ __half g_tth[2][NODE_F + PAD_F];   // combined features, fp16, k-permuted
__device__ int    g_hist[NSEG];               // zero at load; scan re-zeroes each run
__device__ int    g_rowptr[NSEG];
__device__ int    g_cursor[NSEG];             // after scatter: cursor[seg] == segment end
__device__ int    g_total;                    // zero at load; scatter role re-zeroes each run
__device__ int    g_csr[3 * E_EDGES];

struct Job {
    const __half* A; const __half* W; const float* bias; void* outp;
    const float* Hres; const float* skipv; int cin; int mode;
};
struct Jobs { Job j[16]; };

// ---------------- helpers ----------------
__device__ __forceinline__ unsigned pack2(float a, float b) {
    __half2 h = __floats2half2_rn(a, b);
    return *(unsigned*)&h;
}
__device__ __forceinline__ void mma_f16(float* d, const unsigned* a, const unsigned* b) {
    asm volatile(
        "mma.sync.aligned.m16n8k16.row.col.f32.f16.f16.f32 "
        "{%0,%1,%2,%3}, {%4,%5,%6,%7}, {%8,%9}, {%0,%1,%2,%3};"
        : "+f"(d[0]), "+f"(d[1]), "+f"(d[2]), "+f"(d[3])
        : "r"(a[0]), "r"(a[1]), "r"(a[2]), "r"(a[3]), "r"(b[0]), "r"(b[1]));
}
__device__ __forceinline__ void cpa16(unsigned saddr, const void* g) {
    asm volatile("cp.async.cg.shared.global [%0], [%1], 16;" :: "r"(saddr), "l"(g));
}
__device__ __forceinline__ unsigned smem_u32(const void* p) {
    unsigned a;
    asm("{ .reg .u64 t; cvta.to.shared.u64 t, %1; cvt.u32.u64 %0, t; }" : "=r"(a) : "l"(p));
    return a;
}
__device__ __forceinline__ void ld8h_nc(const __half* p, float* f) {
    uint4 u = __ldg((const uint4*)p);
    float2 a;
    a = __half22float2(*(__half2*)&u.x); f[0] = a.x; f[1] = a.y;
    a = __half22float2(*(__half2*)&u.y); f[2] = a.x; f[3] = a.y;
    a = __half22float2(*(__half2*)&u.z); f[4] = a.x; f[5] = a.y;
    a = __half22float2(*(__half2*)&u.w); f[6] = a.x; f[7] = a.y;
}
__device__ __forceinline__ float dot8h(const __half2* qh, uint4 ku) {
    __half2 acc = __hmul2(qh[0], *(__half2*)&ku.x);
    acc = __hfma2(qh[1], *(__half2*)&ku.y, acc);
    acc = __hfma2(qh[2], *(__half2*)&ku.z, acc);
    acc = __hfma2(qh[3], *(__half2*)&ku.w, acc);
    float2 f = __half22float2(acc);
    return f.x + f.y;
}

// ---------------- prep: round inputs + build weights/biases + dst histogram ----------------
#define NGRP  (NODE_F / 16)
#define TOTW  (2048 * 256)
#define TOTB  2048
#define TOTWA (2 * 256 * 256)
#define PREP_BASE (NGRP + TOTW + TOTB + TOTWA)
__device__ __forceinline__ int halfidx(int k) {
    int w = k >> 1, h = k & 1, wi = w & 7;
    int pw = (wi < 4) ? 2 * wi : 2 * wi - 7;
    return ((w >> 3) << 4) + pw * 2 + h;
}
__global__ void prep_kernel(const float* __restrict__ hA, const float* __restrict__ hB,
                            const float* __restrict__ Wq, const float* __restrict__ bq,
                            const float* __restrict__ Wk, const float* __restrict__ bk,
                            const float* __restrict__ Wv, const float* __restrict__ bv,
                            const float* __restrict__ Wa,
                            const float* __restrict__ rel_att, const float* __restrict__ rel_msg,
                            const int* __restrict__ d0, const int* __restrict__ d1,
                            const int* __restrict__ d2, int E) {
    int gid = blockIdx.x * blockDim.x + threadIdx.x;
    if (gid < NGRP) {
        int i = gid;
        #pragma unroll
        for (int t = 0; t < 2; t++) {
            const float* src = t ? hB : hA;
            float4 f0 = ((const float4*)src)[4 * i + 0];
            float4 f1 = ((const float4*)src)[4 * i + 1];
            float4 f2 = ((const float4*)src)[4 * i + 2];
            float4 f3 = ((const float4*)src)[4 * i + 3];
            unsigned W0 = pack2(f0.x, f0.y), W1 = pack2(f0.z, f0.w);
            unsigned W2 = pack2(f1.x, f1.y), W3 = pack2(f1.z, f1.w);
            unsigned W4 = pack2(f2.x, f2.y), W5 = pack2(f2.z, f2.w);
            unsigned W6 = pack2(f3.x, f3.y), W7 = pack2(f3.z, f3.w);
            ((uint4*)g_hrh[t])[2 * i]     = make_uint4(W0, W4, W1, W5);
            ((uint4*)g_hrh[t])[2 * i + 1] = make_uint4(W2, W6, W3, W7);
        }
        return;
    }
    gid -= NGRP;
    if (gid < TOTW) {
        int k = gid & 255;
        int n = gid >> 8;
        int side  = (n < 1280) ? 0 : 1;
        int local = side ? (n - 1280) : n;
        int g = local >> 8, col = local & 255;
        float val;
        if (g == 0) {
            val = Wq[side * 65536 + k * 256 + col];
        } else {
            int r   = side ? 1 : ((g <= 2) ? 0 : 2);
            int isv = side ? (g == 2) : ((g & 1) == 0);
            const float* W  = (isv ? Wv : Wk) + side * 65536 + k * 256 + (col >> 5) * 32;
            const float* rp = (isv ? rel_msg : rel_att) + r * 8192 + (col >> 5) * 1024 + (col & 31);
            float acc = 0.f;
            #pragma unroll
            for (int d = 0; d < 32; d++) acc += W[d] * rp[d * 32];
            val = acc;
        }
        g_WTh[n * 256 + halfidx(k)] = __float2half_rn(val);
        return;
    }
    gid -= TOTW;
    if (gid < TOTB) {
        int n = gid;
        int side  = (n < 1280) ? 0 : 1;
        int local = side ? (n - 1280) : n;
        int g = local >> 8, col = local & 255;
        float val;
        if (g == 0) {
            val = bq[side * 256 + col];
        } else {
            int r   = side ? 1 : ((g <= 2) ? 0 : 2);
            int isv = side ? (g == 2) : ((g & 1) == 0);
            const float* b  = (isv ? bv : bk) + side * 256 + (col >> 5) * 32;
            const float* rp = (isv ? rel_msg : rel_att) + r * 8192 + (col >> 5) * 1024 + (col & 31);
            float acc = 0.f;
            #pragma unroll
            for (int d = 0; d < 32; d++) acc += b[d] * rp[d * 32];
            val = acc;
        }
        g_bc[n] = val;
        return;
    }
    gid -= TOTB;
    if (gid < TOTWA) {
        int i = gid;
        int k = i & 255, nn = (i >> 8) & 255, t = i >> 16;
        g_WaTh[t * 65536 + nn * 256 + halfidx(k)] = __float2half_rn(Wa[t * 65536 + k * 256 + nn]);
        return;
    }
    gid -= TOTWA;
    if (gid < 3 * E) {
        int r = gid / E, e = gid - r * E;
        const int* dd = (r == 0) ? d0 : ((r == 1) ? d1 : d2);
        atomicAdd(&g_hist[r * N_NODES + dd[e]], 1);
    }
}

// ---------------- fp16 mma.sync GEMM (R13 proven) + fused scatter role ----------------
#define SSTR32 40
#define STG_WORDS 10240
#define STG_BYTES 40960u
#define TG_SMEM 81920
__global__ void __launch_bounds__(256, 2) tgemm(
        Jobs jobs, int M, int njobs,
        const int* __restrict__ s0, const int* __restrict__ d0,
        const int* __restrict__ s1, const int* __restrict__ d1,
        const int* __restrict__ s2, const int* __restrict__ d2, int E) {
    extern __shared__ float smem[];
    int tid = threadIdx.x;

    if ((int)blockIdx.x == njobs) {
        int base = blockIdx.y * 256 + tid;
        int stride = gridDim.y * 256;
        if (base == 0) g_total = 0;
        for (int i = base; i < 3 * E; i += stride) {
            int r = i / E, e = i - r * E;
            const int* ss = (r == 0) ? s0 : ((r == 1) ? s1 : s2);
            const int* dd = (r == 0) ? d0 : ((r == 1) ? d1 : d2);
            int pos = atomicAdd(&g_cursor[r * N_NODES + dd[e]], 1);
            g_csr[pos] = ss[e];
        }
        return;
    }

    unsigned sbase = smem_u32(smem);
    Job jb = jobs.j[blockIdx.x];
    int lane = tid & 31, wid = tid >> 5;
    int row0 = blockIdx.y * 128;
    int wm = (wid >> 2) * 64;
    int wn = (wid & 3) * 32;
    int g = lane >> 2, c = lane & 3;

    float acc[4][4][4];
    #pragma unroll
    for (int i = 0; i < 4; i++)
        #pragma unroll
        for (int j = 0; j < 4; j++)
            #pragma unroll
            for (int q = 0; q < 4; q++) acc[i][j][q] = 0.f;

    int r_st[4], jc_st[4];
    #pragma unroll
    for (int i = 0; i < 4; i++) {
        int sl = i * 256 + tid;
        r_st[i] = sl >> 3; jc_st[i] = sl & 7;
    }

    #pragma unroll
    for (int i = 0; i < 4; i++) {
        unsigned so = sbase + (unsigned)(r_st[i] * 160 + jc_st[i] * 16);
        cpa16(so, jb.A + (size_t)(row0 + r_st[i]) * 256 + jc_st[i] * 8);
        cpa16(so + 20480u, jb.W + (size_t)r_st[i] * 256 + jc_st[i] * 8);
    }
    asm volatile("cp.async.commit_group;" ::: "memory");

    #pragma unroll
    for (int ck = 0; ck < 4; ck++) {
        asm volatile("cp.async.wait_group 0;" ::: "memory");
        __syncthreads();
        if (ck + 1 < 4) {
            unsigned stb = sbase + ((ck + 1) & 1) * STG_BYTES;
            #pragma unroll
            for (int i = 0; i < 4; i++) {
                unsigned so = stb + (unsigned)(r_st[i] * 160 + jc_st[i] * 16);
                cpa16(so, jb.A + (size_t)(row0 + r_st[i]) * 256 + (ck + 1) * 64 + jc_st[i] * 8);
                cpa16(so + 20480u, jb.W + (size_t)r_st[i] * 256 + (ck + 1) * 64 + jc_st[i] * 8);
            }
            asm volatile("cp.async.commit_group;" ::: "memory");
        }
        const unsigned* sAw = ((const unsigned*)smem) + (ck & 1) * STG_WORDS;
        const unsigned* sBw = sAw + 5120;
        #pragma unroll
        for (int s = 0; s < 4; s++) {
            unsigned af[4][4], bf[4][2];
            int kc = s * 8 + 2 * c;
            #pragma unroll
            for (int mt = 0; mt < 4; mt++) {
                int m = wm + mt * 16;
                uint2 lo = *(const uint2*)&sAw[(m + g)     * SSTR32 + kc];
                uint2 hi = *(const uint2*)&sAw[(m + g + 8) * SSTR32 + kc];
                af[mt][0] = lo.x; af[mt][1] = hi.x; af[mt][2] = lo.y; af[mt][3] = hi.y;
            }
            #pragma unroll
            for (int nt = 0; nt < 4; nt++) {
                uint2 b = *(const uint2*)&sBw[(wn + nt * 8 + g) * SSTR32 + kc];
                bf[nt][0] = b.x; bf[nt][1] = b.y;
            }
            #pragma unroll
            for (int mt = 0; mt < 4; mt++)
                #pragma unroll
                for (int nt = 0; nt < 4; nt++)
                    mma_f16(acc[mt][nt], af[mt], bf[nt]);
        }
    }

    float alpha = 1.f, beta = 0.f;
    if (jb.mode == 1) {
        float sv = *jb.skipv;
        alpha = 1.f / (1.f + __expf(-sv));
        beta  = 1.f - alpha;
    }
    int cinb = jb.cin + wn;
    #pragma unroll
    for (int mt = 0; mt < 4; mt++) {
        #pragma unroll
        for (int half = 0; half < 2; half++) {
            int row = row0 + wm + mt * 16 + g + half * 8;
            if (row >= M) continue;
            #pragma unroll
            for (int nt = 0; nt < 4; nt++) {
                int lcol = wn + nt * 8 + 2 * c;
                int cin = cinb + nt * 8 + 2 * c;
                float v0 = acc[mt][nt][half * 2 + 0] + jb.bias[lcol];
                float v1 = acc[mt][nt][half * 2 + 1] + jb.bias[lcol + 1];
                if (jb.mode == 1) {
                    float* O = (float*)jb.outp;
                    v0 = v0 * alpha + jb.Hres[(size_t)row * 256 + cin]     * beta;
                    v1 = v1 * alpha + jb.Hres[(size_t)row * 256 + cin + 1] * beta;
                    float2 o; o.x = v0; o.y = v1;
                    *(float2*)(O + (size_t)row * 256 + cin) = o;
                } else {
                    __half* H = (__half*)jb.outp;
                    *(unsigned*)(H + (size_t)row * 256 + cin) = pack2(v0, v1);
                }
            }
        }
    }
}

// ---------------- single-pass CSR scan ----------------
__global__ void scan_kernel() {
    __shared__ int sh[256];
    __shared__ int base;
    int i = blockIdx.x * 256 + threadIdx.x;
    int v = (i < NSEG) ? g_hist[i] : 0;
    sh[threadIdx.x] = v;
    __syncthreads();
    for (int o = 1; o < 256; o <<= 1) {
        int t = (threadIdx.x >= (unsigned)o) ? sh[threadIdx.x - o] : 0;
        __syncthreads();
        sh[threadIdx.x] += t;
        __syncthreads();
    }
    if (threadIdx.x == 255) base = atomicAdd(&g_total, sh[255]);
    __syncthreads();
    int excl = sh[threadIdx.x] - v + base;
    if (i < NSEG) {
        g_rowptr[i] = excl;
        g_cursor[i] = excl;
        g_hist[i] = 0;
    }
}

// ---------------- aggregation: warp per dst of one node type ----------------
__global__ void agg_kernel(int t, const float* __restrict__ rel_pri) {
    int n = (blockIdx.x * blockDim.x + threadIdx.x) >> 5;
    int lane = threadIdx.x & 31;
    if (n >= N_NODES) return;
    const float rs = 0.17677669529663687f;
    int head = lane >> 2;

    uint4 qu = __ldg((const uint4*)(g_Qh[t] + (size_t)n * DIM + 8 * lane));
    __half2 qh[4] = {*(__half2*)&qu.x, *(__half2*)&qu.y, *(__half2*)&qu.z, *(__half2*)&qu.w};

    float outv[8];
    #pragma unroll
    for (int j = 0; j < 8; j++) outv[j] = 0.f;

    int rfirst = t ? 0 : 1;
    int rcount = t ? 1 : 2;
    float scale = t ? 1.f : 0.5f;

    for (int ri = 0; ri < rcount; ri++) {
        int r = rfirst + ri;
        float pr = rel_pri[r * NHEAD + head] * rs;
        int seg = r * N_NODES + n;
        int beg = g_rowptr[seg], end = g_cursor[seg];
        const __half* Kb = g_kh[r];
        const __half* Vb = g_vh[r];
        float a[8];
        #pragma unroll
        for (int j = 0; j < 8; j++) a[j] = 0.f;
        float ssum = 0.f;
        int i = beg;
        for (; i + 1 < end; i += 2) {
            int sn0 = __ldg(&g_csr[i]), sn1 = __ldg(&g_csr[i + 1]);
            uint4 k0 = __ldg((const uint4*)(Kb + (size_t)sn0 * DIM + 8 * lane));
            uint4 k1 = __ldg((const uint4*)(Kb + (size_t)sn1 * DIM + 8 * lane));
            float v0[8], v1[8];
            ld8h_nc(Vb + (size_t)sn0 * DIM + 8 * lane, v0);
            ld8h_nc(Vb + (size_t)sn1 * DIM + 8 * lane, v1);
            float p0 = dot8h(qh, k0);
            float p1 = dot8h(qh, k1);
            p0 += __shfl_xor_sync(0xffffffffu, p0, 2);
            p1 += __shfl_xor_sync(0xffffffffu, p1, 2);
            p0 += __shfl_xor_sync(0xffffffffu, p0, 1);
            p1 += __shfl_xor_sync(0xffffffffu, p1, 1);
            float ex0 = __expf(p0 * pr);
            float ex1 = __expf(p1 * pr);
            ssum += ex0 + ex1;
            #pragma unroll
            for (int j = 0; j < 8; j++) a[j] += ex0 * v0[j] + ex1 * v1[j];
        }
        if (i < end) {
            int sn = __ldg(&g_csr[i]);
            uint4 kk = __ldg((const uint4*)(Kb + (size_t)sn * DIM + 8 * lane));
            float vv[8];
            ld8h_nc(Vb + (size_t)sn * DIM + 8 * lane, vv);
            float p = dot8h(qh, kk);
            p += __shfl_xor_sync(0xffffffffu, p, 2);
            p += __shfl_xor_sync(0xffffffffu, p, 1);
            float ex = __expf(p * pr);
            ssum += ex;
            #pragma unroll
            for (int j = 0; j < 8; j++) a[j] += ex * vv[j];
        }
        float inv = (ssum > 0.f) ? scale / ssum : 0.f;
        #pragma unroll
        for (int j = 0; j < 8; j++) outv[j] += a[j] * inv;
    }

    unsigned* orow = (unsigned*)(g_tth[t] + (size_t)n * DIM);
    #pragma unroll
    for (int j = 0; j < 4; j++) {
        int w = 4 * lane + j;
        int wi = w & 7;
        int pos = (w & ~7) + ((wi < 4) ? 2 * wi : 2 * wi - 7);
        orow[pos] = pack2(outv[2 * j], outv[2 * j + 1]);
    }
}

// ---------------- launch ----------------
extern "C" void kernel_launch(void* const* d_in, const int* in_sizes, int n_in,
                              void* d_out, int out_size) {
    const float* h_A     = (const float*)d_in[0];
    const float* h_B     = (const float*)d_in[1];
    const float* Wk      = (const float*)d_in[2];
    const float* bk      = (const float*)d_in[3];
    const float* Wq      = (const float*)d_in[4];
    const float* bq      = (const float*)d_in[5];
    const float* Wv      = (const float*)d_in[6];
    const float* bv      = (const float*)d_in[7];
    const float* Wa      = (const float*)d_in[8];
    const float* ba      = (const float*)d_in[9];
    const float* rel_att = (const float*)d_in[10];
    const float* rel_msg = (const float*)d_in[11];
    const float* rel_pri = (const float*)d_in[12];
    const float* skip    = (const float*)d_in[13];
    const int*   src[3]  = {(const int*)d_in[14], (const int*)d_in[16], (const int*)d_in[18]};
    const int*   dst[3]  = {(const int*)d_in[15], (const int*)d_in[17], (const int*)d_in[19]};
    const int E = in_sizes[14];
    float* out = (float*)d_out;

    __half *pHr[2], *pQh[2], *pkh[3], *pvh[3], *pWTh, *pWaTh, *ptt[2];
    float *pbc;
    {
        void* base;
        cudaGetSymbolAddress(&base, g_hrh);  pHr[0] = (__half*)base; pHr[1] = (__half*)base + NODE_F + PAD_F;
        cudaGetSymbolAddress(&base, g_Qh);   pQh[0] = (__half*)base; pQh[1] = (__half*)base + NODE_F;
        cudaGetSymbolAddress(&base, g_kh);   for (int r = 0; r < 3; r++) pkh[r] = (__half*)base + (size_t)r * NODE_F;
        cudaGetSymbolAddress(&base, g_vh);   for (int r = 0; r < 3; r++) pvh[r] = (__half*)base + (size_t)r * NODE_F;
        cudaGetSymbolAddress(&base, g_WTh);  pWTh = (__half*)base;
        cudaGetSymbolAddress(&base, g_bc);   pbc = (float*)base;
        cudaGetSymbolAddress(&base, g_WaTh); pWaTh = (__half*)base;
        cudaGetSymbolAddress(&base, g_tth);  ptt[0] = (__half*)base; ptt[1] = (__half*)base + NODE_F + PAD_F;
    }

    cudaFuncSetAttribute(tgemm, cudaFuncAttributeMaxDynamicSharedMemorySize, TG_SMEM);

    // fork resources (created per call; intentionally never destroyed — destroying a
    // capture-referenced stream/event before EndCapture would invalidate the capture)
    cudaStream_t s1;
    cudaEvent_t ev1, ev2;
    cudaStreamCreateWithFlags(&s1, cudaStreamNonBlocking);
    cudaEventCreateWithFlags(&ev1, cudaEventDisableTiming);
    cudaEventCreateWithFlags(&ev2, cudaEventDisableTiming);

    // prep (round + weight build + dst histogram, merged)
    {
        int tot = PREP_BASE + 3 * E;
        prep_kernel<<<(tot + 255) / 256, 256>>>(h_A, h_B, Wq, bq, Wk, bk, Wv, bv, Wa,
                                                rel_att, rel_msg, dst[0], dst[1], dst[2], E);
    }

    // single-pass CSR scan
    scan_kernel<<<(NSEG + 255) / 256, 256>>>();

    int mblocks = (N_NODES + 127) / 128;
    int aggblocks = (N_NODES * 32 + 255) / 256;

    // merged projection GEMMs (16 col-tiles) + fused edge scatter (blockIdx.x==16)
    {
        Jobs jobs;
        __half* targA[5] = {pQh[0], pkh[0], pvh[0], pkh[2], pvh[2]};
        __half* targB[3] = {pQh[1], pkh[1], pvh[1]};
        for (int x = 0; x < 10; x++) {
            int col0 = x * 128;
            jobs.j[x] = { pHr[0], pWTh + (size_t)col0 * 256, pbc + col0,
                          (void*)targA[x >> 1], nullptr, nullptr, (x & 1) * 128, 0 };
        }
        for (int x2 = 0; x2 < 6; x2++) {
            int col0 = 1280 + x2 * 128;
            jobs.j[10 + x2] = { pHr[1], pWTh + (size_t)col0 * 256, pbc + col0,
                                (void*)targB[x2 >> 1], nullptr, nullptr, (x2 & 1) * 128, 0 };
        }
        dim3 grid(17, mblocks);
        tgemm<<<grid, 256, TG_SMEM>>>(jobs, N_NODES, 16,
                                      src[0], dst[0], src[1], dst[1], src[2], dst[2], E);
    }

    // fork: branch B (agg_B -> outGEMM_B) on s1, branch A stays on the main stream
    cudaEventRecord(ev1, 0);
    cudaStreamWaitEvent(s1, ev1, 0);

    // branch B: type-B aggregation + its output GEMM
    agg_kernel<<<aggblocks, 256, 0, s1>>>(1, rel_pri);
    {
        Jobs jobs;
        for (int x = 0; x < 2; x++)
            jobs.j[x] = { ptt[1], pWaTh + 65536 + (size_t)x * 128 * 256, ba + 256 + x * 128,
                          (void*)(out + NODE_F), h_B, skip + 1, x * 128, 1 };
        dim3 grid(2, mblocks);
        tgemm<<<grid, 256, TG_SMEM, s1>>>(jobs, N_NODES, 2,
                                          src[0], dst[0], src[1], dst[1], src[2], dst[2], E);
    }
    cudaEventRecord(ev2, s1);

    // branch A: type-A aggregation + its output GEMM (main stream)
    agg_kernel<<<aggblocks, 256>>>(0, rel_pri);
    {
        Jobs jobs;
        for (int x = 0; x < 2; x++)
            jobs.j[x] = { ptt[0], pWaTh + (size_t)x * 128 * 256, ba + x * 128,
                          (void*)out, h_A, skip, x * 128, 1 };
        dim3 grid(2, mblocks);
        tgemm<<<grid, 256, TG_SMEM>>>(jobs, N_NODES, 2,
                                      src[0], dst[0], src[1], dst[1], src[2], dst[2], E);
    }

    // join branch B back into the main stream
    cudaStreamWaitEvent(0, ev2, 0);
}